// round 12
// baseline (speedup 1.0000x reference)
#include <cuda_runtime.h>
#include <cuda_bf16.h>
#include <mma.h>
#include <cstdint>

using namespace nvcuda;

#define C_SZ   192
#define TOK    262144
#define NWIN   4096
#define HID_SZ 768

// -------- scratch (device globals) --------
__device__ __nv_bfloat16 g_xln [(size_t)TOK * C_SZ];
__device__ float         g_xres[(size_t)TOK * C_SZ];
__device__ __nv_bfloat16 g_qkv [(size_t)TOK * 3 * C_SZ];
__device__ __nv_bfloat16 g_attn[(size_t)TOK * C_SZ];
__device__ float         g_y1  [(size_t)TOK * C_SZ];
__device__ __nv_bfloat16 g_hln [(size_t)TOK * C_SZ];
__device__ __nv_bfloat16 g_hid [(size_t)TOK * HID_SZ];
__device__ __nv_bfloat16 g_wq  [3 * C_SZ * C_SZ];
__device__ __nv_bfloat16 g_wp  [C_SZ * C_SZ];
__device__ __nv_bfloat16 g_w1  [HID_SZ * C_SZ];
__device__ __nv_bfloat16 g_w2  [C_SZ * HID_SZ];

// -------- helpers --------
__device__ __forceinline__ unsigned smem_u32(const void* p) {
    return (unsigned)__cvta_generic_to_shared(p);
}
__device__ __forceinline__ void cp16(void* s, const void* g) {
    asm volatile("cp.async.cg.shared.global [%0], [%1], 16;\n"
                 :: "r"(smem_u32(s)), "l"(g));
}
#define CP_COMMIT asm volatile("cp.async.commit_group;\n" ::: "memory")
#define CP_WAIT(N) asm volatile("cp.async.wait_group %0;\n" :: "n"(N) : "memory")

__device__ __forceinline__ uint32_t pack_bf2(float a, float b) {
    __nv_bfloat162 t = __floats2bfloat162_rn(a, b);
    return *(uint32_t*)&t;
}
__device__ __forceinline__ void ldsm4(uint32_t& r0, uint32_t& r1, uint32_t& r2, uint32_t& r3,
                                      uint32_t addr) {
    asm volatile("ldmatrix.sync.aligned.m8n8.x4.shared.b16 {%0,%1,%2,%3}, [%4];"
                 : "=r"(r0), "=r"(r1), "=r"(r2), "=r"(r3) : "r"(addr));
}
__device__ __forceinline__ void ldsm2(uint32_t& r0, uint32_t& r1, uint32_t addr) {
    asm volatile("ldmatrix.sync.aligned.m8n8.x2.shared.b16 {%0,%1}, [%2];"
                 : "=r"(r0), "=r"(r1) : "r"(addr));
}
__device__ __forceinline__ void ldsm2t(uint32_t& r0, uint32_t& r1, uint32_t addr) {
    asm volatile("ldmatrix.sync.aligned.m8n8.x2.trans.shared.b16 {%0,%1}, [%2];"
                 : "=r"(r0), "=r"(r1) : "r"(addr));
}
__device__ __forceinline__ void mma16816(float* c, uint32_t a0, uint32_t a1, uint32_t a2,
                                         uint32_t a3, uint32_t b0, uint32_t b1) {
    asm volatile(
        "mma.sync.aligned.m16n8k16.row.col.f32.bf16.bf16.f32 "
        "{%0,%1,%2,%3}, {%4,%5,%6,%7}, {%8,%9}, {%0,%1,%2,%3};"
        : "+f"(c[0]), "+f"(c[1]), "+f"(c[2]), "+f"(c[3])
        : "r"(a0), "r"(a1), "r"(a2), "r"(a3), "r"(b0), "r"(b1));
}

// -------- fused weight convert --------
__global__ void cvt_all(const float* __restrict__ a, const float* __restrict__ b,
                        const float* __restrict__ c, const float* __restrict__ d) {
    int i = blockIdx.x * 256 + threadIdx.x;
    if (i < 110592)       g_wq[i]          = __float2bfloat16(a[i]);
    else if (i < 147456)  g_wp[i - 110592] = __float2bfloat16(b[i - 110592]);
    else if (i < 294912)  g_w1[i - 147456] = __float2bfloat16(c[i - 147456]);
    else if (i < 442368)  g_w2[i - 294912] = __float2bfloat16(d[i - 294912]);
}

// -------- LN1: single pass over x (BCHW) -> token-major g_xln (bf16) + g_xres (fp32)
__global__ __launch_bounds__(256) void ln1_kernel(const float* __restrict__ x,
                                                  const float* __restrict__ w,
                                                  const float* __restrict__ b) {
    __shared__ float xs[32 * 193];
    __shared__ float smu[32], srs[32];
    const int tid = threadIdx.x;
    const int pix0 = blockIdx.x * 32;
    const int bidx = pix0 >> 16;
    const int hw0  = pix0 & 65535;
    const float* xb = x + (size_t)bidx * C_SZ * 65536 + hw0;

    #pragma unroll 6
    for (int i = tid; i < 32 * 192; i += 256) {
        int c = i >> 5, p = i & 31;
        xs[p * 193 + c] = xb[(size_t)c * 65536 + p];
    }
    __syncthreads();

    if (tid < 64) {
        int t = tid >> 1, h = tid & 1;
        const float* row = xs + t * 193 + h * 96;
        float s = 0.f, sq = 0.f;
        #pragma unroll 8
        for (int j = 0; j < 96; j++) { float v = row[j]; s += v; sq += v * v; }
        s  += __shfl_xor_sync(0xffffffffu, s, 1);
        sq += __shfl_xor_sync(0xffffffffu, sq, 1);
        if (h == 0) {
            float mu = s * (1.f / C_SZ);
            smu[t] = mu;
            srs[t] = rsqrtf(sq * (1.f / C_SZ) - mu * mu + 1e-5f);
        }
    }
    __syncthreads();

    #pragma unroll 6
    for (int i = tid; i < 32 * 192; i += 256) {
        int p = i / 192, c = i - p * 192;
        float v = xs[p * 193 + c];
        size_t off = (size_t)(pix0 + p) * C_SZ + c;
        g_xres[off] = v;
        g_xln[off]  = __float2bfloat16((v - smu[p]) * srs[p] * w[c] + b[c]);
    }
}

// ===================== GEMM: 128(M) x 96(N) tile, K-step 64, 3-stage pipeline (round-10 proven)
template<int MODE, int K>
__global__ __launch_bounds__(256, 2) void gemm_t(const __nv_bfloat16* __restrict__ A,
                                                 const __nv_bfloat16* __restrict__ W,
                                                 const float* __restrict__ bias,
                                                 int N, void* __restrict__ outp,
                                                 const float* __restrict__ res) {
    extern __shared__ unsigned char dsm[];
    constexpr int STG = 224 * 72 * 2;   // 32256 B per stage
    constexpr int NST = K / 64;
    float* sBias = (float*)(dsm + 3 * STG);

    const int tid = threadIdx.x, warp = tid >> 5, lane = tid & 31;
    const int wm = warp >> 1, wn = warp & 1;
    const int m0 = blockIdx.y * 128, n0 = blockIdx.x * 96;

    if (tid < 96) sBias[tid] = bias[n0 + tid];

    wmma::fragment<wmma::accumulator, 16, 16, 16, float> acc[2][3];
    #pragma unroll
    for (int i = 0; i < 2; i++)
        #pragma unroll
        for (int j = 0; j < 3; j++) wmma::fill_fragment(acc[i][j], 0.f);

    auto load_stage = [&](int buf, int kk) {
        __nv_bfloat16* st = (__nv_bfloat16*)(dsm + buf * STG);
        #pragma unroll
        for (int i = 0; i < 7; i++) {
            int u = tid + i * 256;       // 0..1791
            int row = u >> 3, q = u & 7;
            const __nv_bfloat16* src = (row < 128)
                ? A + (size_t)(m0 + row) * K + kk + q * 8
                : W + (size_t)(n0 + row - 128) * K + kk + q * 8;
            cp16(st + row * 72 + q * 8, src);
        }
    };

    load_stage(0, 0);  CP_COMMIT;
    if (NST > 1) { load_stage(1, 64); CP_COMMIT; }

    #pragma unroll 1
    for (int s = 0; s < NST; s++) {
        if (s + 1 < NST) { CP_WAIT(1); } else { CP_WAIT(0); }
        __syncthreads();
        const __nv_bfloat16* As = (const __nv_bfloat16*)(dsm + (s % 3) * STG);
        const __nv_bfloat16* Bs = As + 128 * 72;
        #pragma unroll
        for (int ksub = 0; ksub < 4; ksub++) {
            wmma::fragment<wmma::matrix_a, 16, 16, 16, __nv_bfloat16, wmma::row_major> fa0, fa1;
            wmma::load_matrix_sync(fa0, As + (wm * 32) * 72 + ksub * 16, 72);
            wmma::load_matrix_sync(fa1, As + (wm * 32 + 16) * 72 + ksub * 16, 72);
            #pragma unroll
            for (int j = 0; j < 3; j++) {
                wmma::fragment<wmma::matrix_b, 16, 16, 16, __nv_bfloat16, wmma::col_major> fb;
                wmma::load_matrix_sync(fb, Bs + (wn * 48 + j * 16) * 72 + ksub * 16, 72);
                wmma::mma_sync(acc[0][j], fa0, fb, acc[0][j]);
                wmma::mma_sync(acc[1][j], fa1, fb, acc[1][j]);
            }
        }
        if (s + 2 < NST) { load_stage((s + 2) % 3, (s + 2) * 64); CP_COMMIT; }
    }
    __syncthreads();

    // epilogue: per warp 16x48 at a time
    float* Ep = (float*)dsm + warp * 832;        // 16 x 52
    const int cbase = n0 + wn * 48;
    #pragma unroll
    for (int h2 = 0; h2 < 2; h2++) {
        wmma::store_matrix_sync(Ep,      acc[h2][0], 52, wmma::mem_row_major);
        wmma::store_matrix_sync(Ep + 16, acc[h2][1], 52, wmma::mem_row_major);
        wmma::store_matrix_sync(Ep + 32, acc[h2][2], 52, wmma::mem_row_major);
        __syncwarp();
        if (MODE == 0 || MODE == 1) {
            #pragma unroll
            for (int e = 0; e < 24; e++) {
                int idx = lane + e * 32;
                int r = idx / 48, c = idx - r * 48;
                float v = Ep[r * 52 + c] + sBias[wn * 48 + c];
                if (MODE == 1) v = 0.5f * v * (1.f + erff(v * 0.70710678118654752f));
                ((__nv_bfloat16*)outp)[(size_t)(m0 + wm * 32 + h2 * 16 + r) * N + cbase + c] =
                    __float2bfloat16(v);
            }
        } else { // MODE 3
            #pragma unroll
            for (int e = 0; e < 24; e++) {
                int idx = lane + e * 32;
                int r = idx / 48, c = idx - r * 48;
                int m = m0 + wm * 32 + h2 * 16 + r;
                Ep[r * 52 + c] += sBias[wn * 48 + c] + res[(size_t)m * 192 + cbase + c];
            }
            __syncwarp();
            int rr = lane & 15;
            int cb2 = (lane >> 4) * 24;
            int m = m0 + wm * 32 + h2 * 16 + rr;
            size_t pixb = (size_t)(m >> 16) * 192 * 65536 + (size_t)(m & 65535);
            #pragma unroll
            for (int cc = 0; cc < 24; cc++) {
                int nn = cbase + cb2 + cc;
                ((float*)outp)[pixb + (size_t)nn * 65536] = Ep[rr * 52 + cb2 + cc];
            }
        }
        __syncwarp();
    }
}

// ===================== proj_ln: proj GEMM (64x192 full-N tile) + residual + LN2 fused ======
// A = g_attn [TOK,192] bf16, W = g_wp [192,192] bf16; out: g_y1 fp32 + g_hln bf16.
#define PSTG 36864   // (64 + 192) rows x 72 halves x 2B per stage
#define PSMEM (2 * PSTG + 1536)

__global__ __launch_bounds__(256, 3) void proj_ln(const float* __restrict__ projb,
                                                  const float* __restrict__ n2w,
                                                  const float* __restrict__ n2b) {
    extern __shared__ unsigned char dsm[];
    float* sBias = (float*)(dsm + 2 * PSTG);
    float* MU = sBias + 192;
    float* RS = MU + 64;
    float* PO = (float*)dsm;                   // 64 x 200 fp32 overlay (post-compute)

    const int tid = threadIdx.x, warp = tid >> 5;
    const int wm = warp >> 2, wn = warp & 3;   // 2 x 4 warp grid: 32-row x 48-col tiles
    const int m0 = blockIdx.x * 64;

    if (tid < 192) sBias[tid] = projb[tid];

    wmma::fragment<wmma::accumulator, 16, 16, 16, float> acc[2][3];
    #pragma unroll
    for (int i = 0; i < 2; i++)
        #pragma unroll
        for (int j = 0; j < 3; j++) wmma::fill_fragment(acc[i][j], 0.f);

    auto load_stage = [&](int buf, int kk) {
        __nv_bfloat16* st = (__nv_bfloat16*)(dsm + buf * PSTG);
        #pragma unroll
        for (int i = 0; i < 8; i++) {
            int u = tid + i * 256;       // 0..2047
            int row = u >> 3, q = u & 7;
            const __nv_bfloat16* src = (row < 64)
                ? g_attn + (size_t)(m0 + row) * 192 + kk + q * 8
                : g_wp + (size_t)(row - 64) * 192 + kk + q * 8;
            cp16(st + row * 72 + q * 8, src);
        }
    };

    load_stage(0, 0);  CP_COMMIT;
    load_stage(1, 64); CP_COMMIT;

    #pragma unroll 1
    for (int s = 0; s < 3; s++) {
        if (s < 2) { CP_WAIT(1); } else { CP_WAIT(0); }
        __syncthreads();
        const __nv_bfloat16* As = (const __nv_bfloat16*)(dsm + (s & 1) * PSTG);
        const __nv_bfloat16* Bs = As + 64 * 72;
        #pragma unroll
        for (int ksub = 0; ksub < 4; ksub++) {
            wmma::fragment<wmma::matrix_a, 16, 16, 16, __nv_bfloat16, wmma::row_major> fa0, fa1;
            wmma::load_matrix_sync(fa0, As + (wm * 32) * 72 + ksub * 16, 72);
            wmma::load_matrix_sync(fa1, As + (wm * 32 + 16) * 72 + ksub * 16, 72);
            #pragma unroll
            for (int j = 0; j < 3; j++) {
                wmma::fragment<wmma::matrix_b, 16, 16, 16, __nv_bfloat16, wmma::col_major> fb;
                wmma::load_matrix_sync(fb, Bs + (wn * 48 + j * 16) * 72 + ksub * 16, 72);
                wmma::mma_sync(acc[0][j], fa0, fb, acc[0][j]);
                wmma::mma_sync(acc[1][j], fa1, fb, acc[1][j]);
            }
        }
        if (s == 0) {
            __syncthreads();          // buffer 0 fully consumed before overwrite
            load_stage(0, 128); CP_COMMIT;
        }
    }
    __syncthreads();

    // accumulators -> PO (64 x 200)
    #pragma unroll
    for (int i = 0; i < 2; i++)
        #pragma unroll
        for (int j = 0; j < 3; j++)
            wmma::store_matrix_sync(PO + (wm * 32 + i * 16) * 200 + wn * 48 + j * 16,
                                    acc[i][j], 200, wmma::mem_row_major);
    __syncthreads();

    // bias + residual -> y1 (fp32) and PO
    #pragma unroll
    for (int i = 0; i < 48; i++) {
        int e = i * 256 + tid;          // 0..12287
        int p = e / 192, c = e - p * 192;
        float v = PO[p * 200 + c] + sBias[c] + g_xres[(size_t)(m0 + p) * 192 + c];
        PO[p * 200 + c] = v;
        g_y1[(size_t)(m0 + p) * 192 + c] = v;
    }
    __syncthreads();

    // LN2 stats: 4 threads per row
    {
        int p = tid >> 2, q = tid & 3;
        float s = 0.f, sq = 0.f;
        #pragma unroll
        for (int j = 0; j < 48; j++) {
            float v = PO[p * 200 + q * 48 + j];
            s += v; sq += v * v;
        }
        s  += __shfl_xor_sync(0xffffffffu, s, 1);
        sq += __shfl_xor_sync(0xffffffffu, sq, 1);
        s  += __shfl_xor_sync(0xffffffffu, s, 2);
        sq += __shfl_xor_sync(0xffffffffu, sq, 2);
        if (q == 0) {
            float mu = s * (1.f / 192.f);
            MU[p] = mu;
            RS[p] = rsqrtf(sq * (1.f / 192.f) - mu * mu + 1e-5f);
        }
    }
    __syncthreads();

    // write hln
    #pragma unroll
    for (int i = 0; i < 48; i++) {
        int e = i * 256 + tid;
        int p = e / 192, c = e - p * 192;
        float v = PO[p * 200 + c];
        g_hln[(size_t)(m0 + p) * 192 + c] =
            __float2bfloat16((v - MU[p]) * RS[p] * n2w[c] + n2b[c]);
    }
}

// -------- window attention: register-resident softmax via mma.sync.m16n8k16
__global__ __launch_bounds__(128, 6) void attn_kernel() {
    __shared__ __align__(16) __nv_bfloat16 qs[64 * 40];
    __shared__ __align__(16) __nv_bfloat16 ks[64 * 40];
    __shared__ __align__(16) __nv_bfloat16 vs[64 * 40];

    const int win  = blockIdx.x;
    const int head = blockIdx.y;
    const int tid  = threadIdx.x;
    const int warp = tid >> 5, lane = tid & 31;
    const float scale = 0.17677669529663687f;

    const int b  = win >> 10;
    const int wh = (win >> 5) & 31;
    const int ww = win & 31;
    const int pixbase = b * 65536 + (wh * 8) * 256 + ww * 8;

    #pragma unroll
    for (int it = 0; it < 2; it++) {
        int u = tid + it * 128;
        int t = u >> 2, seg = u & 3;
        int pix = pixbase + (t >> 3) * 256 + (t & 7);
        const uint4* rp = (const uint4*)(g_qkv + (size_t)pix * (3 * C_SZ) + head * 32);
        *(uint4*)(qs + t * 40 + seg * 8) = rp[seg];
        *(uint4*)(ks + t * 40 + seg * 8) = rp[seg + 24];
        *(uint4*)(vs + t * 40 + seg * 8) = rp[seg + 48];
    }
    __syncthreads();

    uint32_t qa[2][4];
    {
        int mrow = (lane >> 3) & 1, mcol = lane >> 4, r = lane & 7;
        #pragma unroll
        for (int kc = 0; kc < 2; kc++) {
            uint32_t addr = smem_u32(qs + (warp * 16 + mrow * 8 + r) * 40 + kc * 16 + mcol * 8);
            ldsm4(qa[kc][0], qa[kc][1], qa[kc][2], qa[kc][3], addr);
        }
    }
    float sc[8][4];
    #pragma unroll
    for (int j = 0; j < 8; j++) { sc[j][0] = sc[j][1] = sc[j][2] = sc[j][3] = 0.f; }
    #pragma unroll
    for (int j = 0; j < 8; j++) {
        uint32_t base = smem_u32(ks + (j * 8 + (lane & 7)) * 40 + ((lane >> 3) & 1) * 8);
        uint32_t b0, b1;
        ldsm2(b0, b1, base);
        mma16816(sc[j], qa[0][0], qa[0][1], qa[0][2], qa[0][3], b0, b1);
        ldsm2(b0, b1, base + 32);
        mma16816(sc[j], qa[1][0], qa[1][1], qa[1][2], qa[1][3], b0, b1);
    }

    float mxA = -1e30f, mxB = -1e30f;
    #pragma unroll
    for (int j = 0; j < 8; j++) {
        mxA = fmaxf(mxA, fmaxf(sc[j][0], sc[j][1]));
        mxB = fmaxf(mxB, fmaxf(sc[j][2], sc[j][3]));
    }
    mxA = fmaxf(mxA, __shfl_xor_sync(0xffffffffu, mxA, 1));
    mxA = fmaxf(mxA, __shfl_xor_sync(0xffffffffu, mxA, 2));
    mxB = fmaxf(mxB, __shfl_xor_sync(0xffffffffu, mxB, 1));
    mxB = fmaxf(mxB, __shfl_xor_sync(0xffffffffu, mxB, 2));
    float sA = 0.f, sB = 0.f;
    #pragma unroll
    for (int j = 0; j < 8; j++) {
        sc[j][0] = __expf((sc[j][0] - mxA) * scale); sA += sc[j][0];
        sc[j][1] = __expf((sc[j][1] - mxA) * scale); sA += sc[j][1];
        sc[j][2] = __expf((sc[j][2] - mxB) * scale); sB += sc[j][2];
        sc[j][3] = __expf((sc[j][3] - mxB) * scale); sB += sc[j][3];
    }
    sA += __shfl_xor_sync(0xffffffffu, sA, 1);
    sA += __shfl_xor_sync(0xffffffffu, sA, 2);
    sB += __shfl_xor_sync(0xffffffffu, sB, 1);
    sB += __shfl_xor_sync(0xffffffffu, sB, 2);
    const float invA = 1.f / sA, invB = 1.f / sB;

    float o[4][4];
    #pragma unroll
    for (int jn = 0; jn < 4; jn++) { o[jn][0] = o[jn][1] = o[jn][2] = o[jn][3] = 0.f; }
    #pragma unroll
    for (int kc = 0; kc < 4; kc++) {
        uint32_t a0 = pack_bf2(sc[2 * kc][0] * invA,     sc[2 * kc][1] * invA);
        uint32_t a1 = pack_bf2(sc[2 * kc][2] * invB,     sc[2 * kc][3] * invB);
        uint32_t a2 = pack_bf2(sc[2 * kc + 1][0] * invA, sc[2 * kc + 1][1] * invA);
        uint32_t a3 = pack_bf2(sc[2 * kc + 1][2] * invB, sc[2 * kc + 1][3] * invB);
        uint32_t vrow = smem_u32(vs + (kc * 16 + (lane & 15)) * 40);
        #pragma unroll
        for (int jn = 0; jn < 4; jn++) {
            uint32_t b0, b1;
            ldsm2t(b0, b1, vrow + jn * 16);
            mma16816(o[jn], a0, a1, a2, a3, b0, b1);
        }
    }

    {
        int rA = warp * 16 + (lane >> 2);
        int rB = rA + 8;
        int pixA = pixbase + ((rA >> 3) * 256 + (rA & 7));
        int pixB = pixbase + ((rB >> 3) * 256 + (rB & 7));
        __nv_bfloat16* oA = g_attn + (size_t)pixA * C_SZ + head * 32 + (lane & 3) * 2;
        __nv_bfloat16* oB = g_attn + (size_t)pixB * C_SZ + head * 32 + (lane & 3) * 2;
        #pragma unroll
        for (int jn = 0; jn < 4; jn++) {
            *(uint32_t*)(oA + jn * 8) = pack_bf2(o[jn][0], o[jn][1]);
            *(uint32_t*)(oB + jn * 8) = pack_bf2(o[jn][2], o[jn][3]);
        }
    }
}

extern "C" void kernel_launch(void* const* d_in, const int* in_sizes, int n_in,
                              void* d_out, int out_size) {
    const float* x     = (const float*)d_in[0];
    const float* n1w   = (const float*)d_in[1];
    const float* n1b   = (const float*)d_in[2];
    const float* qkvw  = (const float*)d_in[3];
    const float* qkvb  = (const float*)d_in[4];
    const float* projw = (const float*)d_in[5];
    const float* projb = (const float*)d_in[6];
    const float* n2w   = (const float*)d_in[7];
    const float* n2b   = (const float*)d_in[8];
    const float* w1    = (const float*)d_in[9];
    const float* b1    = (const float*)d_in[10];
    const float* w2    = (const float*)d_in[11];
    const float* b2    = (const float*)d_in[12];
    float* out = (float*)d_out;

    void *p_xln, *p_qkv, *p_hln, *p_hid, *p_wq, *p_w1, *p_w2, *p_y1;
    cudaGetSymbolAddress(&p_xln, g_xln);
    cudaGetSymbolAddress(&p_qkv, g_qkv);
    cudaGetSymbolAddress(&p_y1, g_y1);
    cudaGetSymbolAddress(&p_hln, g_hln);
    cudaGetSymbolAddress(&p_hid, g_hid);
    cudaGetSymbolAddress(&p_wq, g_wq);
    cudaGetSymbolAddress(&p_w1, g_w1);
    cudaGetSymbolAddress(&p_w2, g_w2);

    const int GSM = 3 * 32256 + 384;   // 97152 (round-10 proven)
    static bool attr_done = false;
    if (!attr_done) {
        cudaFuncSetAttribute(gemm_t<0,192>, cudaFuncAttributeMaxDynamicSharedMemorySize, GSM);
        cudaFuncSetAttribute(gemm_t<1,192>, cudaFuncAttributeMaxDynamicSharedMemorySize, GSM);
        cudaFuncSetAttribute(gemm_t<3,768>, cudaFuncAttributeMaxDynamicSharedMemorySize, GSM);
        cudaFuncSetAttribute(proj_ln, cudaFuncAttributeMaxDynamicSharedMemorySize, PSMEM);
        attr_done = true;
    }

    // weight convert
    cvt_all<<<1728, 256>>>(qkvw, projw, w1, w2);

    // LN1 -> g_xln (bf16) + g_xres (fp32), token-major
    ln1_kernel<<<TOK/32, 256>>>(x, n1w, n1b);

    // QKV GEMM: [TOK,192] @ [576,192]^T -> g_qkv
    gemm_t<0,192><<<dim3(6, TOK/128), 256, GSM>>>((const __nv_bfloat16*)p_xln,
                                                  (const __nv_bfloat16*)p_wq,
                                                  qkvb, 576, p_qkv, nullptr);

    // window attention -> g_attn (token-major)
    attn_kernel<<<dim3(NWIN, 6), 128>>>();

    // proj + residual + LN2 fused -> g_y1 (fp32) + g_hln (bf16)
    proj_ln<<<TOK/64, 256, PSMEM>>>(projb, n2w, n2b);

    // MLP1 + GELU: [TOK,192] @ [768,192]^T -> g_hid
    gemm_t<1,192><<<dim3(8, TOK/128), 256, GSM>>>((const __nv_bfloat16*)p_hln,
                                                  (const __nv_bfloat16*)p_w1,
                                                  b1, 768, p_hid, nullptr);

    // MLP2 + residual -> BCHW output
    gemm_t<3,768><<<dim3(2, TOK/128), 256, GSM>>>((const __nv_bfloat16*)p_hid,
                                                  (const __nv_bfloat16*)p_w2,
                                                  b2, 192, out, (const float*)p_y1);
}

// round 15
// speedup vs baseline: 1.0981x; 1.0981x over previous
#include <cuda_runtime.h>
#include <cuda_bf16.h>
#include <mma.h>
#include <cstdint>

using namespace nvcuda;

#define C_SZ   192
#define TOK    262144
#define NWIN   4096
#define HID_SZ 768

// -------- scratch (device globals) --------
__device__ __nv_bfloat16 g_xln [(size_t)TOK * C_SZ];
__device__ float         g_xres[(size_t)TOK * C_SZ];
__device__ __nv_bfloat16 g_qkv [(size_t)TOK * 3 * C_SZ];
__device__ __nv_bfloat16 g_attn[(size_t)TOK * C_SZ];
__device__ float         g_y1  [(size_t)TOK * C_SZ];
__device__ __nv_bfloat16 g_hln [(size_t)TOK * C_SZ];
__device__ __nv_bfloat16 g_hid [(size_t)TOK * HID_SZ];
__device__ __nv_bfloat16 g_wq  [3 * C_SZ * C_SZ];
__device__ __nv_bfloat16 g_wp  [C_SZ * C_SZ];
__device__ __nv_bfloat16 g_w1  [HID_SZ * C_SZ];
__device__ __nv_bfloat16 g_w2  [C_SZ * HID_SZ];

// -------- helpers --------
__device__ __forceinline__ unsigned smem_u32(const void* p) {
    return (unsigned)__cvta_generic_to_shared(p);
}
__device__ __forceinline__ void cp16(void* s, const void* g) {
    asm volatile("cp.async.cg.shared.global [%0], [%1], 16;\n"
                 :: "r"(smem_u32(s)), "l"(g));
}
#define CP_COMMIT asm volatile("cp.async.commit_group;\n" ::: "memory")
#define CP_WAIT(N) asm volatile("cp.async.wait_group %0;\n" :: "n"(N) : "memory")

__device__ __forceinline__ uint32_t pack_bf2(float a, float b) {
    __nv_bfloat162 t = __floats2bfloat162_rn(a, b);
    return *(uint32_t*)&t;
}
__device__ __forceinline__ void ldsm4(uint32_t& r0, uint32_t& r1, uint32_t& r2, uint32_t& r3,
                                      uint32_t addr) {
    asm volatile("ldmatrix.sync.aligned.m8n8.x4.shared.b16 {%0,%1,%2,%3}, [%4];"
                 : "=r"(r0), "=r"(r1), "=r"(r2), "=r"(r3) : "r"(addr));
}
__device__ __forceinline__ void ldsm2(uint32_t& r0, uint32_t& r1, uint32_t addr) {
    asm volatile("ldmatrix.sync.aligned.m8n8.x2.shared.b16 {%0,%1}, [%2];"
                 : "=r"(r0), "=r"(r1) : "r"(addr));
}
__device__ __forceinline__ void ldsm2t(uint32_t& r0, uint32_t& r1, uint32_t addr) {
    asm volatile("ldmatrix.sync.aligned.m8n8.x2.trans.shared.b16 {%0,%1}, [%2];"
                 : "=r"(r0), "=r"(r1) : "r"(addr));
}
__device__ __forceinline__ void mma16816(float* c, uint32_t a0, uint32_t a1, uint32_t a2,
                                         uint32_t a3, uint32_t b0, uint32_t b1) {
    asm volatile(
        "mma.sync.aligned.m16n8k16.row.col.f32.bf16.bf16.f32 "
        "{%0,%1,%2,%3}, {%4,%5,%6,%7}, {%8,%9}, {%0,%1,%2,%3};"
        : "+f"(c[0]), "+f"(c[1]), "+f"(c[2]), "+f"(c[3])
        : "r"(a0), "r"(a1), "r"(a2), "r"(a3), "r"(b0), "r"(b1));
}

// -------- fused weight convert --------
__global__ void cvt_all(const float* __restrict__ a, const float* __restrict__ b,
                        const float* __restrict__ c, const float* __restrict__ d) {
    int i = blockIdx.x * 256 + threadIdx.x;
    if (i < 110592)       g_wq[i]          = __float2bfloat16(a[i]);
    else if (i < 147456)  g_wp[i - 110592] = __float2bfloat16(b[i - 110592]);
    else if (i < 294912)  g_w1[i - 147456] = __float2bfloat16(c[i - 147456]);
    else if (i < 442368)  g_w2[i - 294912] = __float2bfloat16(d[i - 294912]);
}

// -------- LN1: single pass over x (BCHW) -> token-major g_xln (bf16) + g_xres (fp32)
__global__ __launch_bounds__(256) void ln1_kernel(const float* __restrict__ x,
                                                  const float* __restrict__ w,
                                                  const float* __restrict__ b) {
    __shared__ float xs[32 * 193];
    __shared__ float smu[32], srs[32];
    const int tid = threadIdx.x;
    const int pix0 = blockIdx.x * 32;
    const int bidx = pix0 >> 16;
    const int hw0  = pix0 & 65535;
    const float* xb = x + (size_t)bidx * C_SZ * 65536 + hw0;

    #pragma unroll 6
    for (int i = tid; i < 32 * 192; i += 256) {
        int c = i >> 5, p = i & 31;
        xs[p * 193 + c] = xb[(size_t)c * 65536 + p];
    }
    __syncthreads();

    if (tid < 64) {
        int t = tid >> 1, h = tid & 1;
        const float* row = xs + t * 193 + h * 96;
        float s = 0.f, sq = 0.f;
        #pragma unroll 8
        for (int j = 0; j < 96; j++) { float v = row[j]; s += v; sq += v * v; }
        s  += __shfl_xor_sync(0xffffffffu, s, 1);
        sq += __shfl_xor_sync(0xffffffffu, sq, 1);
        if (h == 0) {
            float mu = s * (1.f / C_SZ);
            smu[t] = mu;
            srs[t] = rsqrtf(sq * (1.f / C_SZ) - mu * mu + 1e-5f);
        }
    }
    __syncthreads();

    #pragma unroll 6
    for (int i = tid; i < 32 * 192; i += 256) {
        int p = i / 192, c = i - p * 192;
        float v = xs[p * 193 + c];
        size_t off = (size_t)(pix0 + p) * C_SZ + c;
        g_xres[off] = v;
        g_xln[off]  = __float2bfloat16((v - smu[p]) * srs[p] * w[c] + b[c]);
    }
}

// ===================== GEMM: 128(M) x 96(N) tile, K-step 64, 3-stage pipeline (round-10)
// MODE 0: bf16 out; MODE 1: GELU->bf16; MODE 2: fp32 y1=res+v; MODE 3: BCHW out=res+v
template<int MODE, int K>
__global__ __launch_bounds__(256, 2) void gemm_t(const __nv_bfloat16* __restrict__ A,
                                                 const __nv_bfloat16* __restrict__ W,
                                                 const float* __restrict__ bias,
                                                 int N, void* __restrict__ outp,
                                                 const float* __restrict__ res) {
    extern __shared__ unsigned char dsm[];
    constexpr int STG = 224 * 72 * 2;   // 32256 B per stage
    constexpr int NST = K / 64;
    float* sBias = (float*)(dsm + 3 * STG);

    const int tid = threadIdx.x, warp = tid >> 5, lane = tid & 31;
    const int wm = warp >> 1, wn = warp & 1;
    const int m0 = blockIdx.y * 128, n0 = blockIdx.x * 96;

    if (tid < 96) sBias[tid] = bias[n0 + tid];

    wmma::fragment<wmma::accumulator, 16, 16, 16, float> acc[2][3];
    #pragma unroll
    for (int i = 0; i < 2; i++)
        #pragma unroll
        for (int j = 0; j < 3; j++) wmma::fill_fragment(acc[i][j], 0.f);

    auto load_stage = [&](int buf, int kk) {
        __nv_bfloat16* st = (__nv_bfloat16*)(dsm + buf * STG);
        #pragma unroll
        for (int i = 0; i < 7; i++) {
            int u = tid + i * 256;       // 0..1791
            int row = u >> 3, q = u & 7;
            const __nv_bfloat16* src = (row < 128)
                ? A + (size_t)(m0 + row) * K + kk + q * 8
                : W + (size_t)(n0 + row - 128) * K + kk + q * 8;
            cp16(st + row * 72 + q * 8, src);
        }
    };

    load_stage(0, 0);  CP_COMMIT;
    if (NST > 1) { load_stage(1, 64); CP_COMMIT; }

    #pragma unroll 1
    for (int s = 0; s < NST; s++) {
        if (s + 1 < NST) { CP_WAIT(1); } else { CP_WAIT(0); }
        __syncthreads();
        const __nv_bfloat16* As = (const __nv_bfloat16*)(dsm + (s % 3) * STG);
        const __nv_bfloat16* Bs = As + 128 * 72;
        #pragma unroll
        for (int ksub = 0; ksub < 4; ksub++) {
            wmma::fragment<wmma::matrix_a, 16, 16, 16, __nv_bfloat16, wmma::row_major> fa0, fa1;
            wmma::load_matrix_sync(fa0, As + (wm * 32) * 72 + ksub * 16, 72);
            wmma::load_matrix_sync(fa1, As + (wm * 32 + 16) * 72 + ksub * 16, 72);
            #pragma unroll
            for (int j = 0; j < 3; j++) {
                wmma::fragment<wmma::matrix_b, 16, 16, 16, __nv_bfloat16, wmma::col_major> fb;
                wmma::load_matrix_sync(fb, Bs + (wn * 48 + j * 16) * 72 + ksub * 16, 72);
                wmma::mma_sync(acc[0][j], fa0, fb, acc[0][j]);
                wmma::mma_sync(acc[1][j], fa1, fb, acc[1][j]);
            }
        }
        if (s + 2 < NST) { load_stage((s + 2) % 3, (s + 2) * 64); CP_COMMIT; }
    }
    __syncthreads();

    // epilogue: per warp 16x48 at a time
    float* Ep = (float*)dsm + warp * 832;        // 16 x 52
    const int cbase = n0 + wn * 48;
    #pragma unroll
    for (int h2 = 0; h2 < 2; h2++) {
        wmma::store_matrix_sync(Ep,      acc[h2][0], 52, wmma::mem_row_major);
        wmma::store_matrix_sync(Ep + 16, acc[h2][1], 52, wmma::mem_row_major);
        wmma::store_matrix_sync(Ep + 32, acc[h2][2], 52, wmma::mem_row_major);
        __syncwarp();
        if (MODE == 0 || MODE == 1) {
            // vectorized: 16 rows x 24 col-pairs = 384 uint32 units, 12 per lane
            #pragma unroll
            for (int e = 0; e < 12; e++) {
                int u = lane + e * 32;
                int r = u / 24, pc = u - r * 24;
                int c = pc * 2;
                float v0 = Ep[r * 52 + c]     + sBias[wn * 48 + c];
                float v1 = Ep[r * 52 + c + 1] + sBias[wn * 48 + c + 1];
                if (MODE == 1) {
                    v0 = 0.5f * v0 * (1.f + erff(v0 * 0.70710678118654752f));
                    v1 = 0.5f * v1 * (1.f + erff(v1 * 0.70710678118654752f));
                }
                int m = m0 + wm * 32 + h2 * 16 + r;
                *(uint32_t*)((__nv_bfloat16*)outp + (size_t)m * N + cbase + c) = pack_bf2(v0, v1);
            }
        } else if (MODE == 2) {
            #pragma unroll
            for (int e = 0; e < 24; e++) {
                int idx = lane + e * 32;
                int r = idx / 48, c = idx - r * 48;
                int m = m0 + wm * 32 + h2 * 16 + r;
                size_t off = (size_t)m * 192 + cbase + c;
                ((float*)outp)[off] = Ep[r * 52 + c] + sBias[wn * 48 + c] + res[off];
            }
        } else { // MODE 3
            #pragma unroll
            for (int e = 0; e < 24; e++) {
                int idx = lane + e * 32;
                int r = idx / 48, c = idx - r * 48;
                int m = m0 + wm * 32 + h2 * 16 + r;
                Ep[r * 52 + c] += sBias[wn * 48 + c] + res[(size_t)m * 192 + cbase + c];
            }
            __syncwarp();
            int rr = lane & 15;
            int cb2 = (lane >> 4) * 24;
            int m = m0 + wm * 32 + h2 * 16 + rr;
            size_t pixb = (size_t)(m >> 16) * 192 * 65536 + (size_t)(m & 65535);
            #pragma unroll
            for (int cc = 0; cc < 24; cc++) {
                int nn = cbase + cb2 + cc;
                ((float*)outp)[pixb + (size_t)nn * 65536] = Ep[rr * 52 + cb2 + cc];
            }
        }
        __syncwarp();
    }
}

// -------- window attention: register-resident softmax via mma.sync.m16n8k16
// Output staged through this warp's OWN dead qs rows -> full-coverage 16B stores,
// lane pairs covering 32B sectors exactly.
__global__ __launch_bounds__(128, 6) void attn_kernel() {
    __shared__ __align__(16) __nv_bfloat16 qs[64 * 40];
    __shared__ __align__(16) __nv_bfloat16 ks[64 * 40];
    __shared__ __align__(16) __nv_bfloat16 vs[64 * 40];

    const int win  = blockIdx.x;
    const int head = blockIdx.y;
    const int tid  = threadIdx.x;
    const int warp = tid >> 5, lane = tid & 31;
    const float scale = 0.17677669529663687f;

    const int b  = win >> 10;
    const int wh = (win >> 5) & 31;
    const int ww = win & 31;
    const int pixbase = b * 65536 + (wh * 8) * 256 + ww * 8;

    // gather q,k,v (64 tokens x 32 ch each)
    #pragma unroll
    for (int it = 0; it < 2; it++) {
        int u = tid + it * 128;
        int t = u >> 2, seg = u & 3;
        int pix = pixbase + (t >> 3) * 256 + (t & 7);
        const uint4* rp = (const uint4*)(g_qkv + (size_t)pix * (3 * C_SZ) + head * 32);
        *(uint4*)(qs + t * 40 + seg * 8) = rp[seg];
        *(uint4*)(ks + t * 40 + seg * 8) = rp[seg + 24];
        *(uint4*)(vs + t * 40 + seg * 8) = rp[seg + 48];
    }
    __syncthreads();

    // --- S = Q @ K^T
    uint32_t qa[2][4];
    {
        int mrow = (lane >> 3) & 1, mcol = lane >> 4, r = lane & 7;
        #pragma unroll
        for (int kc = 0; kc < 2; kc++) {
            uint32_t addr = smem_u32(qs + (warp * 16 + mrow * 8 + r) * 40 + kc * 16 + mcol * 8);
            ldsm4(qa[kc][0], qa[kc][1], qa[kc][2], qa[kc][3], addr);
        }
    }
    float sc[8][4];
    #pragma unroll
    for (int j = 0; j < 8; j++) { sc[j][0] = sc[j][1] = sc[j][2] = sc[j][3] = 0.f; }
    #pragma unroll
    for (int j = 0; j < 8; j++) {
        uint32_t base = smem_u32(ks + (j * 8 + (lane & 7)) * 40 + ((lane >> 3) & 1) * 8);
        uint32_t b0, b1;
        ldsm2(b0, b1, base);
        mma16816(sc[j], qa[0][0], qa[0][1], qa[0][2], qa[0][3], b0, b1);
        ldsm2(b0, b1, base + 32);
        mma16816(sc[j], qa[1][0], qa[1][1], qa[1][2], qa[1][3], b0, b1);
    }

    // --- register softmax (row A = 16*warp + lane/4; row B = +8)
    float mxA = -1e30f, mxB = -1e30f;
    #pragma unroll
    for (int j = 0; j < 8; j++) {
        mxA = fmaxf(mxA, fmaxf(sc[j][0], sc[j][1]));
        mxB = fmaxf(mxB, fmaxf(sc[j][2], sc[j][3]));
    }
    mxA = fmaxf(mxA, __shfl_xor_sync(0xffffffffu, mxA, 1));
    mxA = fmaxf(mxA, __shfl_xor_sync(0xffffffffu, mxA, 2));
    mxB = fmaxf(mxB, __shfl_xor_sync(0xffffffffu, mxB, 1));
    mxB = fmaxf(mxB, __shfl_xor_sync(0xffffffffu, mxB, 2));
    float sA = 0.f, sB = 0.f;
    #pragma unroll
    for (int j = 0; j < 8; j++) {
        sc[j][0] = __expf((sc[j][0] - mxA) * scale); sA += sc[j][0];
        sc[j][1] = __expf((sc[j][1] - mxA) * scale); sA += sc[j][1];
        sc[j][2] = __expf((sc[j][2] - mxB) * scale); sB += sc[j][2];
        sc[j][3] = __expf((sc[j][3] - mxB) * scale); sB += sc[j][3];
    }
    sA += __shfl_xor_sync(0xffffffffu, sA, 1);
    sA += __shfl_xor_sync(0xffffffffu, sA, 2);
    sB += __shfl_xor_sync(0xffffffffu, sB, 1);
    sB += __shfl_xor_sync(0xffffffffu, sB, 2);
    const float invA = 1.f / sA, invB = 1.f / sB;

    // --- O = P @ V
    float o[4][4];
    #pragma unroll
    for (int jn = 0; jn < 4; jn++) { o[jn][0] = o[jn][1] = o[jn][2] = o[jn][3] = 0.f; }
    #pragma unroll
    for (int kc = 0; kc < 4; kc++) {
        uint32_t a0 = pack_bf2(sc[2 * kc][0] * invA,     sc[2 * kc][1] * invA);
        uint32_t a1 = pack_bf2(sc[2 * kc][2] * invB,     sc[2 * kc][3] * invB);
        uint32_t a2 = pack_bf2(sc[2 * kc + 1][0] * invA, sc[2 * kc + 1][1] * invA);
        uint32_t a3 = pack_bf2(sc[2 * kc + 1][2] * invB, sc[2 * kc + 1][3] * invB);
        uint32_t vrow = smem_u32(vs + (kc * 16 + (lane & 15)) * 40);
        #pragma unroll
        for (int jn = 0; jn < 4; jn++) {
            uint32_t b0, b1;
            ldsm2t(b0, b1, vrow + jn * 16);
            mma16816(o[jn], a0, a1, a2, a3, b0, b1);
        }
    }

    // --- store O: stage bf16 tile (16 rows x 32 cols = 16 x 16 uint32) into this
    //     warp's OWN qs rows, then emit ALL 4 uint4 per row (2 per lane), with lane
    //     pairs (2r, 2r+1) covering each 32B sector exactly.
    {
        uint32_t* stg = (uint32_t*)qs + warp * 320;     // within own 320-uint32 region
        int rloc = lane >> 2;                           // 0..7
        int cq = lane & 3;
        #pragma unroll
        for (int jn = 0; jn < 4; jn++) {
            stg[rloc * 16 + jn * 4 + cq]       = pack_bf2(o[jn][0], o[jn][1]);   // row A
            stg[(rloc + 8) * 16 + jn * 4 + cq] = pack_bf2(o[jn][2], o[jn][3]);   // row B
        }
        __syncwarp();
        int row = lane >> 1;                            // 0..15
        int t = warp * 16 + row;
        int pix = pixbase + (t >> 3) * 256 + (t & 7);
        const uint4* src = (const uint4*)(stg + row * 16);
        uint4* dst = (uint4*)(g_attn + (size_t)pix * C_SZ + head * 32);
        #pragma unroll
        for (int h = 0; h < 2; h++) {
            int q4 = h * 2 + (lane & 1);                // {0,1} then {2,3}
            dst[q4] = src[q4];
        }
    }
}

// -------- LN2: warp per token over fp32 y1 --------
__global__ __launch_bounds__(256) void ln2_kernel(const float* __restrict__ w,
                                                  const float* __restrict__ b) {
    int t    = blockIdx.x * 8 + (threadIdx.x >> 5);
    int lane = threadIdx.x & 31;
    const float* row = g_y1 + (size_t)t * C_SZ;
    float v[6];
    float sum = 0.f;
    #pragma unroll
    for (int i = 0; i < 6; i++) { v[i] = row[lane + i * 32]; sum += v[i]; }
    #pragma unroll
    for (int o = 16; o; o >>= 1) sum += __shfl_xor_sync(0xffffffffu, sum, o);
    float mu = sum * (1.f / C_SZ);
    float sq = 0.f;
    #pragma unroll
    for (int i = 0; i < 6; i++) { float d = v[i] - mu; sq += d * d; }
    #pragma unroll
    for (int o = 16; o; o >>= 1) sq += __shfl_xor_sync(0xffffffffu, sq, o);
    float rs = rsqrtf(sq * (1.f / C_SZ) + 1e-5f);
    __nv_bfloat16* out = g_hln + (size_t)t * C_SZ;
    #pragma unroll
    for (int i = 0; i < 6; i++) {
        int c = lane + i * 32;
        out[c] = __float2bfloat16((v[i] - mu) * rs * w[c] + b[c]);
    }
}

extern "C" void kernel_launch(void* const* d_in, const int* in_sizes, int n_in,
                              void* d_out, int out_size) {
    const float* x     = (const float*)d_in[0];
    const float* n1w   = (const float*)d_in[1];
    const float* n1b   = (const float*)d_in[2];
    const float* qkvw  = (const float*)d_in[3];
    const float* qkvb  = (const float*)d_in[4];
    const float* projw = (const float*)d_in[5];
    const float* projb = (const float*)d_in[6];
    const float* n2w   = (const float*)d_in[7];
    const float* n2b   = (const float*)d_in[8];
    const float* w1    = (const float*)d_in[9];
    const float* b1    = (const float*)d_in[10];
    const float* w2    = (const float*)d_in[11];
    const float* b2    = (const float*)d_in[12];
    float* out = (float*)d_out;

    void *p_xln, *p_qkv, *p_attn, *p_y1, *p_hln, *p_hid, *p_wq, *p_wp, *p_w1, *p_w2, *p_xres;
    cudaGetSymbolAddress(&p_xln, g_xln);
    cudaGetSymbolAddress(&p_xres, g_xres);
    cudaGetSymbolAddress(&p_qkv, g_qkv);
    cudaGetSymbolAddress(&p_attn, g_attn);
    cudaGetSymbolAddress(&p_y1, g_y1);
    cudaGetSymbolAddress(&p_hln, g_hln);
    cudaGetSymbolAddress(&p_hid, g_hid);
    cudaGetSymbolAddress(&p_wq, g_wq);
    cudaGetSymbolAddress(&p_wp, g_wp);
    cudaGetSymbolAddress(&p_w1, g_w1);
    cudaGetSymbolAddress(&p_w2, g_w2);

    const int GSM = 3 * 32256 + 384;   // 97152 (round-10 proven)
    static bool attr_done = false;
    if (!attr_done) {
        cudaFuncSetAttribute(gemm_t<0,192>, cudaFuncAttributeMaxDynamicSharedMemorySize, GSM);
        cudaFuncSetAttribute(gemm_t<1,192>, cudaFuncAttributeMaxDynamicSharedMemorySize, GSM);
        cudaFuncSetAttribute(gemm_t<2,192>, cudaFuncAttributeMaxDynamicSharedMemorySize, GSM);
        cudaFuncSetAttribute(gemm_t<3,768>, cudaFuncAttributeMaxDynamicSharedMemorySize, GSM);
        attr_done = true;
    }

    // weight convert
    cvt_all<<<1728, 256>>>(qkvw, projw, w1, w2);

    // LN1 -> g_xln (bf16) + g_xres (fp32), token-major
    ln1_kernel<<<TOK/32, 256>>>(x, n1w, n1b);

    // QKV GEMM: [TOK,192] @ [576,192]^T -> g_qkv
    gemm_t<0,192><<<dim3(6, TOK/128), 256, GSM>>>((const __nv_bfloat16*)p_xln,
                                                  (const __nv_bfloat16*)p_wq,
                                                  qkvb, 576, p_qkv, nullptr);

    // window attention -> g_attn (token-major)
    attn_kernel<<<dim3(NWIN, 6), 128>>>();

    // proj + residual -> g_y1 (fp32, token-major)
    gemm_t<2,192><<<dim3(2, TOK/128), 256, GSM>>>((const __nv_bfloat16*)p_attn,
                                                  (const __nv_bfloat16*)p_wp,
                                                  projb, 192, p_y1, (const float*)p_xres);

    // LN2 -> g_hln
    ln2_kernel<<<TOK/8, 256>>>(n2w, n2b);

    // MLP1 + GELU: [TOK,192] @ [768,192]^T -> g_hid
    gemm_t<1,192><<<dim3(8, TOK/128), 256, GSM>>>((const __nv_bfloat16*)p_hln,
                                                  (const __nv_bfloat16*)p_w1,
                                                  b1, 768, p_hid, nullptr);

    // MLP2 + residual -> BCHW output
    gemm_t<3,768><<<dim3(2, TOK/128), 256, GSM>>>((const __nv_bfloat16*)p_hid,
                                                  (const __nv_bfloat16*)p_w2,
                                                  b2, 192, out, (const float*)p_y1);
}